// round 2
// baseline (speedup 1.0000x reference)
#include <cuda_runtime.h>
#include <cuda_bf16.h>
#include <cstdint>

#define BATCH 2048
#define CAND  16
#define DIM   256
#define NROWS (BATCH*CAND)          // 32768
#define WIN   3
#define ADJW  (2*WIN*CAND)          // 96
#define OUTW  (DIM + ADJW + 1)      // 353
#define THRED 0.8f
#define CHUNK 16                    // batches per neigh-block (rolling window)

// bf16 copy of cand_emb with rows normalized to unit length (16 MB scratch)
__device__ __nv_bfloat16 g_embn[(size_t)NROWS * DIM];

// ---------------------------------------------------------------------------
// K1: per-row L2-normalize fp32 -> bf16. One warp per row.
// ---------------------------------------------------------------------------
__global__ __launch_bounds__(256) void k_prep(const float* __restrict__ emb) {
    int warp = (blockIdx.x * blockDim.x + threadIdx.x) >> 5;
    int lane = threadIdx.x & 31;
    if (warp >= NROWS) return;
    const float4* src = reinterpret_cast<const float4*>(emb + (size_t)warp * DIM);
    float4 v0 = src[lane * 2];
    float4 v1 = src[lane * 2 + 1];
    float ss = v0.x*v0.x + v0.y*v0.y + v0.z*v0.z + v0.w*v0.w
             + v1.x*v1.x + v1.y*v1.y + v1.z*v1.z + v1.w*v1.w;
    #pragma unroll
    for (int off = 16; off; off >>= 1) ss += __shfl_xor_sync(0xffffffffu, ss, off);
    float inv = rsqrtf(fmaxf(ss, 1e-24f));
    __nv_bfloat162 o[4];
    o[0] = __floats2bfloat162_rn(v0.x * inv, v0.y * inv);
    o[1] = __floats2bfloat162_rn(v0.z * inv, v0.w * inv);
    o[2] = __floats2bfloat162_rn(v1.x * inv, v1.y * inv);
    o[3] = __floats2bfloat162_rn(v1.z * inv, v1.w * inv);
    uint4 pk = *reinterpret_cast<uint4*>(o);
    reinterpret_cast<uint4*>(g_embn + (size_t)warp * DIM)[lane] = pk;
}

// ---------------------------------------------------------------------------
// K2: neighbor-mean (output cols [0,256)). Rolling 7-batch register window.
// blockDim = (64, 4): x = float4 chunk of dim, y = candidate sub-slot.
// grid = (BATCH/CHUNK, 4).
// ---------------------------------------------------------------------------
__global__ __launch_bounds__(256) void k_neigh(const float* __restrict__ emb,
                                               const int* __restrict__ nm,
                                               float* __restrict__ out) {
    const int d4 = threadIdx.x;                       // 0..63
    const int c  = blockIdx.y * 4 + threadIdx.y;      // 0..15
    const int b0 = blockIdx.x * CHUNK;

    auto loadE = [&](int bb) -> float4 {
        if ((unsigned)bb < BATCH)
            return reinterpret_cast<const float4*>(emb)[((size_t)bb * CAND + c) * (DIM / 4) + d4];
        return make_float4(0.f, 0.f, 0.f, 0.f);
    };
    auto loadM = [&](int bb) -> float {
        if ((unsigned)bb < BATCH) return (float)nm[bb * CAND + c];
        return 0.f;
    };

    // w[i] = emb row at batch b-3+i (for current b); m[i] = mask at batch b-3+i (i<6)
    float4 w[7];
    float  m[6];
    #pragma unroll
    for (int i = 0; i < 7; i++) w[i] = loadE(b0 - 3 + i);
    #pragma unroll
    for (int i = 0; i < 6; i++) m[i] = loadM(b0 - 3 + i);

    #pragma unroll
    for (int s = 0; s < CHUNK; s++) {
        const int b = b0 + s;
        // left gates use masks of source rows b-1..b-k; right gates use b..b+k-1
        const float L1 = m[2], L2 = m[2] * m[1], L3 = m[2] * m[1] * m[0];
        const float R1 = m[3], R2 = m[3] * m[4], R3 = m[3] * m[4] * m[5];
        float4 acc;
        acc.x = (w[2].x*L1 + w[1].x*L2 + w[0].x*L3 + w[4].x*R1 + w[5].x*R2 + w[6].x*R3) * (1.f/6.f);
        acc.y = (w[2].y*L1 + w[1].y*L2 + w[0].y*L3 + w[4].y*R1 + w[5].y*R2 + w[6].y*R3) * (1.f/6.f);
        acc.z = (w[2].z*L1 + w[1].z*L2 + w[0].z*L3 + w[4].z*R1 + w[5].z*R2 + w[6].z*R3) * (1.f/6.f);
        acc.w = (w[2].w*L1 + w[1].w*L2 + w[0].w*L3 + w[4].w*R1 + w[5].w*R2 + w[6].w*R3) * (1.f/6.f);
        float* o = out + (size_t)(b * CAND + c) * OUTW + d4 * 4;  // rows are 353 floats: scalar stores
        o[0] = acc.x; o[1] = acc.y; o[2] = acc.z; o[3] = acc.w;
        // slide window
        #pragma unroll
        for (int i = 0; i < 6; i++) w[i] = w[i + 1];
        w[6] = loadE(b + 4);
        #pragma unroll
        for (int i = 0; i < 5; i++) m[i] = m[i + 1];
        m[5] = loadM(b + 3);
    }
}

// ---------------------------------------------------------------------------
// K3: adjacency (output cols [256,353)). One block per batch b.
// 7 bf16 normalized tiles in smem; warps 0..5 run mma.sync bf16 16x16x256
// against neighbor copies (left1..3, right1..3); gate, threshold, L1-norm.
// ---------------------------------------------------------------------------
#define BPAD 264                     // padded bf16 row stride (bank-conflict free frags)
#define SMB_ELEMS (7 * CAND * BPAD)  // 29568 bf16
#define SIMPAD 104

__global__ __launch_bounds__(256) void k_sim(const int* __restrict__ nm,
                                             float* __restrict__ out) {
    extern __shared__ __align__(16) char smraw[];
    __nv_bfloat16* sm   = reinterpret_cast<__nv_bfloat16*>(smraw);          // [7][16][BPAD]
    float* simbuf = reinterpret_cast<float*>(smraw + SMB_ELEMS * 2);        // [16][SIMPAD]
    float* gates  = simbuf + CAND * SIMPAD;                                 // [6][16]
    float* invs   = gates + 6 * CAND;                                       // [16]

    const int b = blockIdx.x;
    const int t = threadIdx.x;

    // --- load 7 batches (b-3..b+3) of normalized bf16 rows; OOB -> zeros ---
    #pragma unroll
    for (int it = 0; it < 14; it++) {
        int cid = it * 256 + t;          // 3584 uint4 chunks total (512/batch-slot)
        int a   = cid >> 9;              // batch slot 0..6
        int rem = cid & 511;
        int row = rem >> 5;              // 0..15
        int kc  = rem & 31;              // uint4 chunk within row
        int bb  = b - 3 + a;
        uint4 val = make_uint4(0u, 0u, 0u, 0u);
        if ((unsigned)bb < BATCH)
            val = reinterpret_cast<const uint4*>(g_embn)[((size_t)bb * CAND + row) * (DIM / 8) + kc];
        *reinterpret_cast<uint4*>(&sm[(a * CAND + row) * BPAD + kc * 8]) = val;
    }

    // --- gates g[copy][j]: copy 0..2 = left k=1..3, copy 3..5 = right k=1..3 ---
    if (t < 6 * CAND) {
        int copy = t >> 4, j = t & 15;
        float g = 1.f;
        if (copy < 3) {
            int k = copy + 1;
            if (b - k < 0) g = 0.f;
            else { for (int q = 1; q <= k; q++) g *= (float)nm[(b - q) * CAND + j]; }
        } else {
            int k = copy - 2;
            if (b + k >= BATCH) g = 0.f;
            else { for (int q = 0; q < k; q++) g *= (float)nm[(b + q) * CAND + j]; }
        }
        gates[copy * CAND + j] = g;
    }
    __syncthreads();

    const int w = t >> 5, lane = t & 31;
    if (w < 6) {
        // copy w -> batch slot: left k -> 3-k, right k -> 3+k
        const int a = (w < 3) ? (2 - w) : (w + 1);
        const int g = lane >> 2, tg = lane & 3;
        const __nv_bfloat16* A  = &sm[3 * CAND * BPAD];     // center batch
        const __nv_bfloat16* Bp = &sm[a * CAND * BPAD];     // neighbor copy
        float acc0[4] = {0.f, 0.f, 0.f, 0.f};               // j 0..7
        float acc1[4] = {0.f, 0.f, 0.f, 0.f};               // j 8..15
        #pragma unroll
        for (int kt = 0; kt < 16; kt++) {
            const int k0 = kt * 16 + tg * 2;
            uint32_t ra0 = *(const uint32_t*)&A[g * BPAD + k0];
            uint32_t ra1 = *(const uint32_t*)&A[(g + 8) * BPAD + k0];
            uint32_t ra2 = *(const uint32_t*)&A[g * BPAD + k0 + 8];
            uint32_t ra3 = *(const uint32_t*)&A[(g + 8) * BPAD + k0 + 8];
            uint32_t rb0 = *(const uint32_t*)&Bp[g * BPAD + k0];
            uint32_t rb1 = *(const uint32_t*)&Bp[g * BPAD + k0 + 8];
            uint32_t rc0 = *(const uint32_t*)&Bp[(g + 8) * BPAD + k0];
            uint32_t rc1 = *(const uint32_t*)&Bp[(g + 8) * BPAD + k0 + 8];
            asm volatile(
                "mma.sync.aligned.m16n8k16.row.col.f32.bf16.bf16.f32 "
                "{%0,%1,%2,%3}, {%4,%5,%6,%7}, {%8,%9}, {%0,%1,%2,%3};\n"
                : "+f"(acc0[0]), "+f"(acc0[1]), "+f"(acc0[2]), "+f"(acc0[3])
                : "r"(ra0), "r"(ra1), "r"(ra2), "r"(ra3), "r"(rb0), "r"(rb1));
            asm volatile(
                "mma.sync.aligned.m16n8k16.row.col.f32.bf16.bf16.f32 "
                "{%0,%1,%2,%3}, {%4,%5,%6,%7}, {%8,%9}, {%0,%1,%2,%3};\n"
                : "+f"(acc1[0]), "+f"(acc1[1]), "+f"(acc1[2]), "+f"(acc1[3])
                : "r"(ra0), "r"(ra1), "r"(ra2), "r"(ra3), "r"(rc0), "r"(rc1));
        }
        // threshold (keep (0.8,1] clamped to <=1, else 0), then gate
        const int jb = tg * 2;
        const float g0 = gates[w * CAND + jb],     g1 = gates[w * CAND + jb + 1];
        const float g2 = gates[w * CAND + jb + 8], g3 = gates[w * CAND + jb + 9];
        auto thr = [](float v, float ge) {
            v = (v > THRED) ? fminf(v, 1.f) : 0.f;
            return v * ge;
        };
        const int colb = w * CAND;
        simbuf[g * SIMPAD + colb + jb]           = thr(acc0[0], g0);
        simbuf[g * SIMPAD + colb + jb + 1]       = thr(acc0[1], g1);
        simbuf[(g + 8) * SIMPAD + colb + jb]     = thr(acc0[2], g0);
        simbuf[(g + 8) * SIMPAD + colb + jb + 1] = thr(acc0[3], g1);
        simbuf[g * SIMPAD + colb + jb + 8]       = thr(acc1[0], g2);
        simbuf[g * SIMPAD + colb + jb + 9]       = thr(acc1[1], g3);
        simbuf[(g + 8) * SIMPAD + colb + jb + 8] = thr(acc1[2], g2);
        simbuf[(g + 8) * SIMPAD + colb + jb + 9] = thr(acc1[3], g3);
    }
    __syncthreads();

    if (t < CAND) {
        float s = 0.f;
        #pragma unroll 8
        for (int cc = 0; cc < ADJW; cc++) s += simbuf[t * SIMPAD + cc];
        invs[t] = 1.0f / fmaxf(s + 1.0f, 1e-12f);
    }
    __syncthreads();

    for (int idx = t; idx < CAND * (ADJW + 1); idx += 256) {
        int i  = idx / (ADJW + 1);
        int cc = idx % (ADJW + 1);
        float v = (cc < ADJW) ? simbuf[i * SIMPAD + cc] : 1.0f;
        out[(size_t)(b * CAND + i) * OUTW + DIM + cc] = v * invs[i];
    }
}

// ---------------------------------------------------------------------------
extern "C" void kernel_launch(void* const* d_in, const int* in_sizes, int n_in,
                              void* d_out, int out_size) {
    (void)in_sizes; (void)n_in; (void)out_size;
    const float* emb = (const float*)d_in[0];
    const int*   nm  = (const int*)d_in[1];
    float*       out = (float*)d_out;

    const int smem_bytes = SMB_ELEMS * 2 + (CAND * SIMPAD + 6 * CAND + CAND) * 4;
    cudaFuncSetAttribute(k_sim, cudaFuncAttributeMaxDynamicSharedMemorySize, smem_bytes);

    k_prep<<<NROWS / 8, 256>>>(emb);

    dim3 nb(64, 4);
    dim3 ng(BATCH / CHUNK, 4);
    k_neigh<<<ng, nb>>>(emb, nm, out);

    k_sim<<<BATCH, 256, smem_bytes>>>(nm, out);
}

// round 4
// speedup vs baseline: 1.2121x; 1.2121x over previous
#include <cuda_runtime.h>
#include <cuda_bf16.h>
#include <cstdint>

#define BATCH 2048
#define CAND  16
#define DIM   256
#define NROWS (BATCH*CAND)          // 32768
#define ADJW  96                    // 2*3*16
#define OUTW  (DIM + ADJW + 1)      // 353
#define THRED 0.8f
#define CHUNK 16                    // batches per k_neigh block

// ---- fused sim kernel geometry ----
#define NB     16                   // batches per block
#define SLOTS  (NB + 6)             // 22 batch tiles incl. +-3 halo
#define BPAD   232                  // bf16 row stride (464B = odd multiple of 16B banks)
#define FTHR   512                  // threads (16 warps)

#define OFF_TILES  0
#define SZ_TILES   (SLOTS * CAND * BPAD * 2)            // 163328 B
#define OFF_GATES  (OFF_TILES + SZ_TILES)
#define SZ_GATES   (NB * 6 * CAND * 4)                  // 6144 B
#define OFF_RSUM   (OFF_GATES + SZ_GATES)
#define SZ_RSUM    (NB * 6 * CAND * 4)                  // 6144 B
#define OFF_INVS   (OFF_RSUM + SZ_RSUM)
#define SZ_INVS    (NB * CAND * 4)                      // 1024 B
#define SMEM_TOTAL (OFF_INVS + SZ_INVS)                 // 176640 B < 192K

// ---------------------------------------------------------------------------
// K_neigh: neighbor-mean (output cols [0,256)). Rolling 7-batch window.
// ---------------------------------------------------------------------------
__global__ __launch_bounds__(256) void k_neigh(const float* __restrict__ emb,
                                               const int* __restrict__ nm,
                                               float* __restrict__ out) {
    const int d4 = threadIdx.x;                       // 0..63
    const int c  = blockIdx.y * 4 + threadIdx.y;      // 0..15
    const int b0 = blockIdx.x * CHUNK;

    auto loadE = [&](int bb) -> float4 {
        if ((unsigned)bb < BATCH)
            return reinterpret_cast<const float4*>(emb)[((size_t)bb * CAND + c) * (DIM / 4) + d4];
        return make_float4(0.f, 0.f, 0.f, 0.f);
    };
    auto loadM = [&](int bb) -> float {
        if ((unsigned)bb < BATCH) return (float)nm[bb * CAND + c];
        return 0.f;
    };

    float4 w[7];
    float  m[6];
    #pragma unroll
    for (int i = 0; i < 7; i++) w[i] = loadE(b0 - 3 + i);
    #pragma unroll
    for (int i = 0; i < 6; i++) m[i] = loadM(b0 - 3 + i);

    #pragma unroll
    for (int s = 0; s < CHUNK; s++) {
        const int b = b0 + s;
        const float L1 = m[2], L2 = m[2] * m[1], L3 = m[2] * m[1] * m[0];
        const float R1 = m[3], R2 = m[3] * m[4], R3 = m[3] * m[4] * m[5];
        float4 acc;
        acc.x = (w[2].x*L1 + w[1].x*L2 + w[0].x*L3 + w[4].x*R1 + w[5].x*R2 + w[6].x*R3) * (1.f/6.f);
        acc.y = (w[2].y*L1 + w[1].y*L2 + w[0].y*L3 + w[4].y*R1 + w[5].y*R2 + w[6].y*R3) * (1.f/6.f);
        acc.z = (w[2].z*L1 + w[1].z*L2 + w[0].z*L3 + w[4].z*R1 + w[5].z*R2 + w[6].z*R3) * (1.f/6.f);
        acc.w = (w[2].w*L1 + w[1].w*L2 + w[0].w*L3 + w[4].w*R1 + w[5].w*R2 + w[6].w*R3) * (1.f/6.f);
        float* o = out + (size_t)(b * CAND + c) * OUTW + d4 * 4;
        o[0] = acc.x; o[1] = acc.y; o[2] = acc.z; o[3] = acc.w;
        #pragma unroll
        for (int i = 0; i < 6; i++) w[i] = w[i + 1];
        w[6] = loadE(b + 4);
        #pragma unroll
        for (int i = 0; i < 5; i++) m[i] = m[i + 1];
        m[5] = loadM(b + 3);
    }
}

// ---------------------------------------------------------------------------
// K_fused: normalize (fp32->bf16, fused, no scratch) + band cosine adjacency
// (output cols [256,353)). One block per NB=16 batches; 22 halo tiles in smem.
// ---------------------------------------------------------------------------
__global__ __launch_bounds__(FTHR) void k_fused(const float* __restrict__ emb,
                                                const int* __restrict__ nm,
                                                float* __restrict__ out) {
    extern __shared__ __align__(16) char smraw[];
    __nv_bfloat16* tiles = reinterpret_cast<__nv_bfloat16*>(smraw + OFF_TILES); // [22][16][BPAD]
    float* gates = reinterpret_cast<float*>(smraw + OFF_GATES);                 // [NB][6][16]
    float* rsum  = reinterpret_cast<float*>(smraw + OFF_RSUM);                  // [NB][6][16]
    float* invs  = reinterpret_cast<float*>(smraw + OFF_INVS);                  // [NB][16]

    const int b0   = blockIdx.x * NB;
    const int t    = threadIdx.x;
    const int wid  = t >> 5;
    const int lane = t & 31;

    // ---- load + normalize: 352 rows, warp-per-row round robin ----
    for (int r = wid; r < SLOTS * CAND; r += 16) {
        const int bb = b0 - 3 + (r >> 4);
        float4 v0 = make_float4(0.f, 0.f, 0.f, 0.f);
        float4 v1 = v0;
        if ((unsigned)bb < BATCH) {
            const float4* src = reinterpret_cast<const float4*>(
                emb + ((size_t)bb * CAND + (r & 15)) * DIM);
            v0 = src[lane * 2];
            v1 = src[lane * 2 + 1];
        }
        float ss = v0.x*v0.x + v0.y*v0.y + v0.z*v0.z + v0.w*v0.w
                 + v1.x*v1.x + v1.y*v1.y + v1.z*v1.z + v1.w*v1.w;
        #pragma unroll
        for (int off = 16; off; off >>= 1) ss += __shfl_xor_sync(0xffffffffu, ss, off);
        float inv = rsqrtf(fmaxf(ss, 1e-24f));
        __nv_bfloat162 o[4];
        o[0] = __floats2bfloat162_rn(v0.x * inv, v0.y * inv);
        o[1] = __floats2bfloat162_rn(v0.z * inv, v0.w * inv);
        o[2] = __floats2bfloat162_rn(v1.x * inv, v1.y * inv);
        o[3] = __floats2bfloat162_rn(v1.z * inv, v1.w * inv);
        *reinterpret_cast<uint4*>(&tiles[(size_t)r * BPAD + lane * 8]) = *reinterpret_cast<uint4*>(o);
    }

    // ---- gates: [bi][cp][j]; cp 0..2 = left k=1..3, 3..5 = right k=1..3 ----
    for (int idx = t; idx < NB * 6 * CAND; idx += FTHR) {
        const int bi = idx / (6 * CAND);
        const int rem = idx % (6 * CAND);
        const int cp = rem >> 4, j = rem & 15;
        const int b = b0 + bi;
        float g = 1.f;
        if (cp < 3) {
            const int k = cp + 1;
            if (b - k < 0) g = 0.f;
            else { for (int q = 1; q <= k; q++) g *= (float)nm[(b - q) * CAND + j]; }
        } else {
            const int k = cp - 2;
            if (b + k >= BATCH) g = 0.f;
            else { for (int q = 0; q < k; q++) g *= (float)nm[(b + q) * CAND + j]; }
        }
        gates[idx] = g;
    }
    __syncthreads();

    // ---- MMA phase: 96 tasks (bi,cp); warp wid does tasks wid+16q ----
    const int g  = lane >> 2;           // 0..7
    const int tg = lane & 3;            // 0..3
    const int jb = tg * 2;
    float simreg[6][8];

    #pragma unroll
    for (int q = 0; q < 6; q++) {
        const int tau = wid + 16 * q;   // 0..95
        const int bi = tau / 6, cp = tau % 6;
        const int aslot = bi + 3;
        const int bslot = (cp < 3) ? (bi + 2 - cp) : (bi + 1 + cp);
        const __nv_bfloat16* A  = &tiles[(size_t)aslot * CAND * BPAD];
        const __nv_bfloat16* Bp = &tiles[(size_t)bslot * CAND * BPAD];

        float acc0[4] = {0.f, 0.f, 0.f, 0.f};
        float acc1[4] = {0.f, 0.f, 0.f, 0.f};
        #pragma unroll
        for (int kt = 0; kt < 16; kt++) {
            const int k0 = kt * 16 + jb;
            uint32_t ra0 = *(const uint32_t*)&A[g * BPAD + k0];
            uint32_t ra1 = *(const uint32_t*)&A[(g + 8) * BPAD + k0];
            uint32_t ra2 = *(const uint32_t*)&A[g * BPAD + k0 + 8];
            uint32_t ra3 = *(const uint32_t*)&A[(g + 8) * BPAD + k0 + 8];
            uint32_t rb0 = *(const uint32_t*)&Bp[g * BPAD + k0];
            uint32_t rb1 = *(const uint32_t*)&Bp[g * BPAD + k0 + 8];
            uint32_t rc0 = *(const uint32_t*)&Bp[(g + 8) * BPAD + k0];
            uint32_t rc1 = *(const uint32_t*)&Bp[(g + 8) * BPAD + k0 + 8];
            asm volatile(
                "mma.sync.aligned.m16n8k16.row.col.f32.bf16.bf16.f32 "
                "{%0,%1,%2,%3}, {%4,%5,%6,%7}, {%8,%9}, {%0,%1,%2,%3};\n"
                : "+f"(acc0[0]), "+f"(acc0[1]), "+f"(acc0[2]), "+f"(acc0[3])
                : "r"(ra0), "r"(ra1), "r"(ra2), "r"(ra3), "r"(rb0), "r"(rb1));
            asm volatile(
                "mma.sync.aligned.m16n8k16.row.col.f32.bf16.bf16.f32 "
                "{%0,%1,%2,%3}, {%4,%5,%6,%7}, {%8,%9}, {%0,%1,%2,%3};\n"
                : "+f"(acc1[0]), "+f"(acc1[1]), "+f"(acc1[2]), "+f"(acc1[3])
                : "r"(ra0), "r"(ra1), "r"(ra2), "r"(ra3), "r"(rc0), "r"(rc1));
        }
        const float* gp = &gates[(bi * 6 + cp) * CAND];
        const float g0 = gp[jb], g1 = gp[jb + 1], g2 = gp[jb + 8], g3 = gp[jb + 9];
        auto thr = [](float v, float ge) {
            v = (v > THRED) ? fminf(v, 1.f) : 0.f;
            return v * ge;
        };
        simreg[q][0] = thr(acc0[0], g0);
        simreg[q][1] = thr(acc0[1], g1);
        simreg[q][2] = thr(acc0[2], g0);
        simreg[q][3] = thr(acc0[3], g1);
        simreg[q][4] = thr(acc1[0], g2);
        simreg[q][5] = thr(acc1[1], g3);
        simreg[q][6] = thr(acc1[2], g2);
        simreg[q][7] = thr(acc1[3], g3);

        // per-row partial sums for this (bi,cp): reduce over the 4 tg lanes
        float sA = simreg[q][0] + simreg[q][1] + simreg[q][4] + simreg[q][5]; // row g
        float sB = simreg[q][2] + simreg[q][3] + simreg[q][6] + simreg[q][7]; // row g+8
        sA += __shfl_xor_sync(0xffffffffu, sA, 1);
        sA += __shfl_xor_sync(0xffffffffu, sA, 2);
        sB += __shfl_xor_sync(0xffffffffu, sB, 1);
        sB += __shfl_xor_sync(0xffffffffu, sB, 2);
        if (tg == 0) {
            rsum[(bi * 6 + cp) * CAND + g]     = sA;
            rsum[(bi * 6 + cp) * CAND + g + 8] = sB;
        }
    }
    __syncthreads();

    // ---- invs: per output row 1 / (L1 sum + ones col) ----
    if (t < NB * CAND) {
        const int bi = t >> 4, i = t & 15;
        float s = 1.0f;
        #pragma unroll
        for (int cp = 0; cp < 6; cp++) s += rsum[(bi * 6 + cp) * CAND + i];
        invs[t] = 1.0f / fmaxf(s, 1e-12f);
    }
    __syncthreads();

    // ---- normalized writes ----
    #pragma unroll
    for (int q = 0; q < 6; q++) {
        const int tau = wid + 16 * q;
        const int bi = tau / 6, cp = tau % 6;
        const float ivA = invs[bi * 16 + g];
        const float ivB = invs[bi * 16 + g + 8];
        float* oA = out + (size_t)((b0 + bi) * CAND + g)     * OUTW + DIM + cp * CAND + jb;
        float* oB = out + (size_t)((b0 + bi) * CAND + g + 8) * OUTW + DIM + cp * CAND + jb;
        oA[0] = simreg[q][0] * ivA;  oA[1] = simreg[q][1] * ivA;
        oA[8] = simreg[q][4] * ivA;  oA[9] = simreg[q][5] * ivA;
        oB[0] = simreg[q][2] * ivB;  oB[1] = simreg[q][3] * ivB;
        oB[8] = simreg[q][6] * ivB;  oB[9] = simreg[q][7] * ivB;
    }
    if (t < NB * CAND) {
        out[(size_t)(b0 * CAND + t) * OUTW + DIM + ADJW] = invs[t];  // ones column * inv
    }
}

// ---------------------------------------------------------------------------
extern "C" void kernel_launch(void* const* d_in, const int* in_sizes, int n_in,
                              void* d_out, int out_size) {
    (void)in_sizes; (void)n_in; (void)out_size;
    const float* emb = (const float*)d_in[0];
    const int*   nm  = (const int*)d_in[1];
    float*       out = (float*)d_out;

    (void)cudaFuncSetAttribute(k_fused, cudaFuncAttributeMaxDynamicSharedMemorySize,
                               SMEM_TOTAL);

    dim3 nb(64, 4);
    dim3 ng(BATCH / CHUNK, 4);
    k_neigh<<<ng, nb>>>(emb, nm, out);

    k_fused<<<BATCH / NB, FTHR, SMEM_TOTAL>>>(emb, nm, out);
}

// round 5
// speedup vs baseline: 1.4790x; 1.2202x over previous
#include <cuda_runtime.h>
#include <cuda_bf16.h>
#include <cstdint>

#define BATCH 2048
#define CAND  16
#define DIM   256
#define ADJW  96                    // 2*3*16
#define OUTW  (DIM + ADJW + 1)      // 353
#define THRED 0.8f
#define CHUNK 32                    // batches per k_neigh block

// ---- fused sim kernel geometry ----
#define NB     8                    // batches per block
#define SLOTS  (NB + 6)             // 14 batch tiles incl. +-3 halo
#define BPAD   232                  // bf16 row stride (word stride 116 == 20 mod 32)
#define FTHR   512                  // threads (16 warps)

#define OFF_TILES  0
#define SZ_TILES   (SLOTS * CAND * BPAD * 2)            // 103936 B
#define OFF_GATES  (OFF_TILES + SZ_TILES)
#define SZ_GATES   (NB * 6 * CAND * 4)                  // 3072 B
#define OFF_RSUM   (OFF_GATES + SZ_GATES)
#define SZ_RSUM    (NB * 6 * CAND * 4)                  // 3072 B
#define OFF_INVS   (OFF_RSUM + SZ_RSUM)
#define SZ_INVS    (NB * CAND * 4)                      // 512 B
#define SMEM_TOTAL (OFF_INVS + SZ_INVS)                 // 110592 B -> 2 CTAs/SM

// ---------------------------------------------------------------------------
// K_neigh: neighbor-mean (output cols [0,256)). Rolling 7-batch window.
// ---------------------------------------------------------------------------
__global__ __launch_bounds__(256) void k_neigh(const float* __restrict__ emb,
                                               const int* __restrict__ nm,
                                               float* __restrict__ out) {
    const int d4 = threadIdx.x;                       // 0..63
    const int c  = blockIdx.y * 4 + threadIdx.y;      // 0..15
    const int b0 = blockIdx.x * CHUNK;

    auto loadE = [&](int bb) -> float4 {
        if ((unsigned)bb < BATCH)
            return reinterpret_cast<const float4*>(emb)[((size_t)bb * CAND + c) * (DIM / 4) + d4];
        return make_float4(0.f, 0.f, 0.f, 0.f);
    };
    auto loadM = [&](int bb) -> float {
        if ((unsigned)bb < BATCH) return (float)nm[bb * CAND + c];
        return 0.f;
    };

    float4 w[7];
    float  m[6];
    #pragma unroll
    for (int i = 0; i < 7; i++) w[i] = loadE(b0 - 3 + i);
    #pragma unroll
    for (int i = 0; i < 6; i++) m[i] = loadM(b0 - 3 + i);

    #pragma unroll 8
    for (int s = 0; s < CHUNK; s++) {
        const int b = b0 + s;
        const float L1 = m[2], L2 = m[2] * m[1], L3 = m[2] * m[1] * m[0];
        const float R1 = m[3], R2 = m[3] * m[4], R3 = m[3] * m[4] * m[5];
        float4 acc;
        acc.x = (w[2].x*L1 + w[1].x*L2 + w[0].x*L3 + w[4].x*R1 + w[5].x*R2 + w[6].x*R3) * (1.f/6.f);
        acc.y = (w[2].y*L1 + w[1].y*L2 + w[0].y*L3 + w[4].y*R1 + w[5].y*R2 + w[6].y*R3) * (1.f/6.f);
        acc.z = (w[2].z*L1 + w[1].z*L2 + w[0].z*L3 + w[4].z*R1 + w[5].z*R2 + w[6].z*R3) * (1.f/6.f);
        acc.w = (w[2].w*L1 + w[1].w*L2 + w[0].w*L3 + w[4].w*R1 + w[5].w*R2 + w[6].w*R3) * (1.f/6.f);
        float* o = out + (size_t)(b * CAND + c) * OUTW + d4 * 4;
        o[0] = acc.x; o[1] = acc.y; o[2] = acc.z; o[3] = acc.w;
        #pragma unroll
        for (int i = 0; i < 6; i++) w[i] = w[i + 1];
        w[6] = loadE(b + 4);
        #pragma unroll
        for (int i = 0; i < 5; i++) m[i] = m[i + 1];
        m[5] = loadM(b + 3);
    }
}

// ---------------------------------------------------------------------------
// K_fused: fused normalize (fp32->bf16) + band cosine adjacency
// (output cols [256,353)). One block per NB=8 batches; 14 halo tiles in smem.
// Warp w handles bi = w/2, cps {0,1,2} (w even) or {3,4,5} (w odd):
// A fragment loaded once per kt and reused across the 3 cp MMAs.
// ---------------------------------------------------------------------------
__global__ __launch_bounds__(FTHR, 2) void k_fused(const float* __restrict__ emb,
                                                   const int* __restrict__ nm,
                                                   float* __restrict__ out) {
    extern __shared__ __align__(16) char smraw[];
    __nv_bfloat16* tiles = reinterpret_cast<__nv_bfloat16*>(smraw + OFF_TILES); // [14][16][BPAD]
    float* gates = reinterpret_cast<float*>(smraw + OFF_GATES);                 // [NB][6][16]
    float* rsum  = reinterpret_cast<float*>(smraw + OFF_RSUM);                  // [NB][6][16]
    float* invs  = reinterpret_cast<float*>(smraw + OFF_INVS);                  // [NB][16]

    const int b0   = blockIdx.x * NB;
    const int t    = threadIdx.x;
    const int wid  = t >> 5;
    const int lane = t & 31;

    // ---- load + normalize: 224 rows, warp-per-row round robin ----
    for (int r = wid; r < SLOTS * CAND; r += 16) {
        const int bb = b0 - 3 + (r >> 4);
        float4 v0 = make_float4(0.f, 0.f, 0.f, 0.f);
        float4 v1 = v0;
        if ((unsigned)bb < BATCH) {
            const float4* src = reinterpret_cast<const float4*>(
                emb + ((size_t)bb * CAND + (r & 15)) * DIM);
            v0 = src[lane * 2];
            v1 = src[lane * 2 + 1];
        }
        float ss = v0.x*v0.x + v0.y*v0.y + v0.z*v0.z + v0.w*v0.w
                 + v1.x*v1.x + v1.y*v1.y + v1.z*v1.z + v1.w*v1.w;
        #pragma unroll
        for (int off = 16; off; off >>= 1) ss += __shfl_xor_sync(0xffffffffu, ss, off);
        float inv = rsqrtf(fmaxf(ss, 1e-24f));
        __nv_bfloat162 o[4];
        o[0] = __floats2bfloat162_rn(v0.x * inv, v0.y * inv);
        o[1] = __floats2bfloat162_rn(v0.z * inv, v0.w * inv);
        o[2] = __floats2bfloat162_rn(v1.x * inv, v1.y * inv);
        o[3] = __floats2bfloat162_rn(v1.z * inv, v1.w * inv);
        *reinterpret_cast<uint4*>(&tiles[(size_t)r * BPAD + lane * 8]) = *reinterpret_cast<uint4*>(o);
    }

    // ---- gates: [bi][cp][j]; cp 0..2 = left k=1..3, 3..5 = right k=1..3 ----
    for (int idx = t; idx < NB * 6 * CAND; idx += FTHR) {
        const int bi = idx / (6 * CAND);
        const int rem = idx % (6 * CAND);
        const int cp = rem >> 4, j = rem & 15;
        const int b = b0 + bi;
        float g = 1.f;
        if (cp < 3) {
            const int k = cp + 1;
            if (b - k < 0) g = 0.f;
            else { for (int q = 1; q <= k; q++) g *= (float)nm[(b - q) * CAND + j]; }
        } else {
            const int k = cp - 2;
            if (b + k >= BATCH) g = 0.f;
            else { for (int q = 0; q < k; q++) g *= (float)nm[(b + q) * CAND + j]; }
        }
        gates[idx] = g;
    }
    __syncthreads();

    // ---- MMA phase ----
    const int g  = lane >> 2;           // 0..7
    const int tg = lane & 3;            // 0..3
    const int jb = tg * 2;
    const int bi = wid >> 1;            // 0..7
    const int cpb = (wid & 1) * 3;      // 0 or 3

    const __nv_bfloat16* A = &tiles[(size_t)(bi + 3) * CAND * BPAD];
    const __nv_bfloat16* Bp[3];
    #pragma unroll
    for (int e = 0; e < 3; e++) {
        const int cp = cpb + e;
        const int bslot = (cp < 3) ? (bi + 2 - cp) : (bi + 1 + cp);
        Bp[e] = &tiles[(size_t)bslot * CAND * BPAD];
    }

    float acc[3][8];
    #pragma unroll
    for (int e = 0; e < 3; e++)
        #pragma unroll
        for (int x = 0; x < 8; x++) acc[e][x] = 0.f;

    #pragma unroll
    for (int kt = 0; kt < 16; kt++) {
        const int k0 = kt * 16 + jb;
        const uint32_t ra0 = *(const uint32_t*)&A[g * BPAD + k0];
        const uint32_t ra1 = *(const uint32_t*)&A[(g + 8) * BPAD + k0];
        const uint32_t ra2 = *(const uint32_t*)&A[g * BPAD + k0 + 8];
        const uint32_t ra3 = *(const uint32_t*)&A[(g + 8) * BPAD + k0 + 8];
        #pragma unroll
        for (int e = 0; e < 3; e++) {
            const uint32_t rb0 = *(const uint32_t*)&Bp[e][g * BPAD + k0];
            const uint32_t rb1 = *(const uint32_t*)&Bp[e][g * BPAD + k0 + 8];
            const uint32_t rc0 = *(const uint32_t*)&Bp[e][(g + 8) * BPAD + k0];
            const uint32_t rc1 = *(const uint32_t*)&Bp[e][(g + 8) * BPAD + k0 + 8];
            asm volatile(
                "mma.sync.aligned.m16n8k16.row.col.f32.bf16.bf16.f32 "
                "{%0,%1,%2,%3}, {%4,%5,%6,%7}, {%8,%9}, {%0,%1,%2,%3};\n"
                : "+f"(acc[e][0]), "+f"(acc[e][1]), "+f"(acc[e][2]), "+f"(acc[e][3])
                : "r"(ra0), "r"(ra1), "r"(ra2), "r"(ra3), "r"(rb0), "r"(rb1));
            asm volatile(
                "mma.sync.aligned.m16n8k16.row.col.f32.bf16.bf16.f32 "
                "{%0,%1,%2,%3}, {%4,%5,%6,%7}, {%8,%9}, {%0,%1,%2,%3};\n"
                : "+f"(acc[e][4]), "+f"(acc[e][5]), "+f"(acc[e][6]), "+f"(acc[e][7])
                : "r"(ra0), "r"(ra1), "r"(ra2), "r"(ra3), "r"(rc0), "r"(rc1));
        }
    }

    // ---- threshold + gate (in place), per-row partial sums ----
    #pragma unroll
    for (int e = 0; e < 3; e++) {
        const int cp = cpb + e;
        const float* gp = &gates[(bi * 6 + cp) * CAND];
        const float g0 = gp[jb], g1 = gp[jb + 1], g2 = gp[jb + 8], g3 = gp[jb + 9];
        auto thr = [](float v, float ge) {
            v = (v > THRED) ? fminf(v, 1.f) : 0.f;
            return v * ge;
        };
        acc[e][0] = thr(acc[e][0], g0);
        acc[e][1] = thr(acc[e][1], g1);
        acc[e][2] = thr(acc[e][2], g0);
        acc[e][3] = thr(acc[e][3], g1);
        acc[e][4] = thr(acc[e][4], g2);
        acc[e][5] = thr(acc[e][5], g3);
        acc[e][6] = thr(acc[e][6], g2);
        acc[e][7] = thr(acc[e][7], g3);

        float sA = acc[e][0] + acc[e][1] + acc[e][4] + acc[e][5]; // row g
        float sB = acc[e][2] + acc[e][3] + acc[e][6] + acc[e][7]; // row g+8
        sA += __shfl_xor_sync(0xffffffffu, sA, 1);
        sA += __shfl_xor_sync(0xffffffffu, sA, 2);
        sB += __shfl_xor_sync(0xffffffffu, sB, 1);
        sB += __shfl_xor_sync(0xffffffffu, sB, 2);
        if (tg == 0) {
            rsum[(bi * 6 + cp) * CAND + g]     = sA;
            rsum[(bi * 6 + cp) * CAND + g + 8] = sB;
        }
    }
    __syncthreads();

    // ---- invs: per output row 1 / (L1 sum + ones col) ----
    if (t < NB * CAND) {
        const int tb = t >> 4, i = t & 15;
        float s = 1.0f;
        #pragma unroll
        for (int cp = 0; cp < 6; cp++) s += rsum[(tb * 6 + cp) * CAND + i];
        invs[t] = 1.0f / fmaxf(s, 1e-12f);
    }
    __syncthreads();

    // ---- normalized writes ----
    const float ivA = invs[bi * 16 + g];
    const float ivB = invs[bi * 16 + g + 8];
    #pragma unroll
    for (int e = 0; e < 3; e++) {
        const int cp = cpb + e;
        float* oA = out + (size_t)((b0 + bi) * CAND + g)     * OUTW + DIM + cp * CAND + jb;
        float* oB = out + (size_t)((b0 + bi) * CAND + g + 8) * OUTW + DIM + cp * CAND + jb;
        oA[0] = acc[e][0] * ivA;  oA[1] = acc[e][1] * ivA;
        oA[8] = acc[e][4] * ivA;  oA[9] = acc[e][5] * ivA;
        oB[0] = acc[e][2] * ivB;  oB[1] = acc[e][3] * ivB;
        oB[8] = acc[e][6] * ivB;  oB[9] = acc[e][7] * ivB;
    }
    if (t < NB * CAND) {
        out[(size_t)(b0 * CAND + t) * OUTW + DIM + ADJW] = invs[t];  // ones column * inv
    }
}

// ---------------------------------------------------------------------------
extern "C" void kernel_launch(void* const* d_in, const int* in_sizes, int n_in,
                              void* d_out, int out_size) {
    (void)in_sizes; (void)n_in; (void)out_size;
    const float* emb = (const float*)d_in[0];
    const int*   nm  = (const int*)d_in[1];
    float*       out = (float*)d_out;

    (void)cudaFuncSetAttribute(k_fused, cudaFuncAttributeMaxDynamicSharedMemorySize,
                               SMEM_TOTAL);

    dim3 nb(64, 4);
    dim3 ng(BATCH / CHUNK, 4);
    k_neigh<<<ng, nb>>>(emb, nm, out);

    k_fused<<<BATCH / NB, FTHR, SMEM_TOTAL>>>(emb, nm, out);
}